// round 16
// baseline (speedup 1.0000x reference)
#include <cuda_runtime.h>
#include <cuda_fp16.h>
#include <math.h>
#include <stdint.h>

// ---------------------------------------------------------------------------
// GCN 2-layer forward:
//   h1 = tanh( Anorm @ (x @ W1) + b1 )
//   h2 = tanh( Anorm @ (h1 @ W2) + b2 )
//
// R15: (1) split-pipeline — agg1 runs in two node-halves; GEMM2 (row-
// parallel) starts on the side stream as soon as the first half of h1 is
// ready, overlapping the second agg1 half. (2) agg1 edge loop unrolled 4x
// (R7-R10 aggregate experiments were masked by the serial scan; retesting
// clean). fp16 mma m16n8k16 + ldmatrix GEMM (R14), multi-block scan (R11).
//
// edge_index arrives as INT32 (JAX x64-disabled downcasts the int64 request).
// ---------------------------------------------------------------------------

#define NNODES_MAX 50000
#define NEDGES_MAX 800000
#define D_IN  256
#define D_H1  256
#define D_H2  128

__device__ __half g_hh[(size_t)NNODES_MAX * D_H1];  // fp16 GEMM output (h)
__device__ __half g_ah[(size_t)NNODES_MAX * D_H1];  // fp16 agg1 output (GEMM2 A)
__device__ __half g_xh[(size_t)NNODES_MAX * D_IN];  // fp16 copy of x
__device__ __half g_w1h[D_IN * D_H1];               // fp16 W1
__device__ __half g_w2h[D_H1 * D_H2];               // fp16 W2
__device__ float  g_dinv[NNODES_MAX];

__device__ int g_deg[NNODES_MAX];        // zero at load; re-zeroed by k_apply
__device__ int g_start[NNODES_MAX + 1];
__device__ int g_cursor[NNODES_MAX];
__device__ int g_src[NEDGES_MAX];

#define SCAN_T 256
#define SCAN_NB ((NNODES_MAX + SCAN_T - 1) / SCAN_T)   // 196
__device__ int g_part[SCAN_NB];
__device__ int g_partpref[SCAN_NB];

// GEMM tiling (fp16): block 128x128, BK=32, 4 stages.
#define A_STR_H 40               // 32 + 8 pad (halves)
#define B_STR_H 136              // 128 + 8 pad (halves)
#define STAGES 4
#define ASTAGE_H (128 * A_STR_H)
#define BSTAGE_H (32 * B_STR_H)
#define MMA_SMEM_BYTES ((STAGES * (ASTAGE_H + BSTAGE_H)) * 2)   // 75776

template<int L> __global__ void k_mma(int Mofs, int M, int N, int K);

// Side stream + events (pre-main; no device-memory allocations).
static cudaStream_t s_side = nullptr;
static cudaEvent_t  s_evFork = nullptr, s_evJoin = nullptr;
static cudaEvent_t  s_evA1a = nullptr, s_evA1b = nullptr;
static cudaEvent_t  s_evM2a = nullptr, s_evM2b = nullptr;
namespace {
struct StreamInit {
    StreamInit() {
        cudaStreamCreateWithFlags(&s_side, cudaStreamNonBlocking);
        cudaEventCreateWithFlags(&s_evFork, cudaEventDisableTiming);
        cudaEventCreateWithFlags(&s_evJoin, cudaEventDisableTiming);
        cudaEventCreateWithFlags(&s_evA1a, cudaEventDisableTiming);
        cudaEventCreateWithFlags(&s_evA1b, cudaEventDisableTiming);
        cudaEventCreateWithFlags(&s_evM2a, cudaEventDisableTiming);
        cudaEventCreateWithFlags(&s_evM2b, cudaEventDisableTiming);
        cudaFuncSetAttribute(k_mma<1>, cudaFuncAttributeMaxDynamicSharedMemorySize, MMA_SMEM_BYTES);
        cudaFuncSetAttribute(k_mma<2>, cudaFuncAttributeMaxDynamicSharedMemorySize, MMA_SMEM_BYTES);
    }
};
static StreamInit s_streamInit;
}

// ---------------------------- CSR build ------------------------------------

__global__ void k_deg_count(const int* __restrict__ col, int E) {
    int stride = gridDim.x * blockDim.x;
    for (int e = blockIdx.x * blockDim.x + threadIdx.x; e < E; e += stride)
        atomicAdd(&g_deg[col[e]], 1);
}

__global__ __launch_bounds__(SCAN_T) void k_partial(int n) {
    __shared__ int s[SCAN_T];
    int t = threadIdx.x;
    int i = blockIdx.x * SCAN_T + t;
    s[t] = (i < n) ? g_deg[i] : 0;
    __syncthreads();
    #pragma unroll
    for (int off = SCAN_T / 2; off > 0; off >>= 1) {
        if (t < off) s[t] += s[t + off];
        __syncthreads();
    }
    if (t == 0) g_part[blockIdx.x] = s[0];
}

__global__ __launch_bounds__(SCAN_T) void k_scanpart(int nb) {
    __shared__ int s[SCAN_T];
    int t = threadIdx.x;
    int my = (t < nb) ? g_part[t] : 0;
    s[t] = my;
    __syncthreads();
    #pragma unroll
    for (int off = 1; off < SCAN_T; off <<= 1) {
        int v = (t >= off) ? s[t - off] : 0;
        __syncthreads();
        s[t] += v;
        __syncthreads();
    }
    if (t < nb) g_partpref[t] = s[t] - my;   // exclusive
}

__global__ __launch_bounds__(SCAN_T) void k_apply(int n) {
    __shared__ int s[SCAN_T];
    int t = threadIdx.x;
    int i = blockIdx.x * SCAN_T + t;
    int d = (i < n) ? g_deg[i] : 0;
    s[t] = d;
    __syncthreads();
    #pragma unroll
    for (int off = 1; off < SCAN_T; off <<= 1) {
        int v = (t >= off) ? s[t - off] : 0;
        __syncthreads();
        s[t] += v;
        __syncthreads();
    }
    int ex = s[t] - d + g_partpref[blockIdx.x];
    if (i < n) {
        g_deg[i] = 0;                          // restore for next graph replay
        g_start[i] = ex;
        g_cursor[i] = ex;
        g_dinv[i] = rsqrtf((float)(d + 1));    // +1 self loop
        if (i == n - 1) g_start[n] = ex + d;
    }
}

__global__ void k_csr_fill(const int* __restrict__ row, const int* __restrict__ col, int E) {
    int stride = gridDim.x * blockDim.x;
    for (int e = blockIdx.x * blockDim.x + threadIdx.x; e < E; e += stride) {
        int slot = atomicAdd(&g_cursor[col[e]], 1);
        g_src[slot] = row[e];
    }
}

// --------------------------- math helpers ----------------------------------

__device__ __forceinline__ float fast_tanh(float x) {
    float ax = fabsf(x);
    float t, r;
    asm("ex2.approx.f32 %0, %1;" : "=f"(t) : "f"(ax * -2.885390081777927f)); // -2*log2(e)
    asm("rcp.approx.f32 %0, %1;" : "=f"(r) : "f"(1.0f + t));
    float y = fmaf(-2.0f * t, r, 1.0f);
    return copysignf(y, x);
}

__device__ __forceinline__ void mma_f16(
    float& c0, float& c1, float& c2, float& c3,
    uint32_t a0, uint32_t a1, uint32_t a2, uint32_t a3,
    uint32_t b0, uint32_t b1)
{
    asm volatile(
        "mma.sync.aligned.m16n8k16.row.col.f32.f16.f16.f32 "
        "{%0,%1,%2,%3}, {%4,%5,%6,%7}, {%8,%9}, {%0,%1,%2,%3};"
        : "+f"(c0), "+f"(c1), "+f"(c2), "+f"(c3)
        : "r"(a0), "r"(a1), "r"(a2), "r"(a3), "r"(b0), "r"(b1));
}

__device__ __forceinline__ void ldmat_x4(uint32_t& r0, uint32_t& r1,
                                         uint32_t& r2, uint32_t& r3, uint32_t addr)
{
    asm volatile("ldmatrix.sync.aligned.m8n8.x4.shared.b16 {%0,%1,%2,%3}, [%4];"
                 : "=r"(r0), "=r"(r1), "=r"(r2), "=r"(r3) : "r"(addr));
}
__device__ __forceinline__ void ldmat_x2t(uint32_t& r0, uint32_t& r1, uint32_t addr)
{
    asm volatile("ldmatrix.sync.aligned.m8n8.x2.trans.shared.b16 {%0,%1}, [%2];"
                 : "=r"(r0), "=r"(r1) : "r"(addr));
}

__device__ __forceinline__ void cp_async16(uint32_t smem_dst, const void* gsrc, bool pred) {
    int sz = pred ? 16 : 0;     // src-size 0 -> 16B zero-fill, no global read
    asm volatile("cp.async.cg.shared.global [%0], [%1], 16, %2;\n"
                 :: "r"(smem_dst), "l"(gsrc), "r"(sz) : "memory");
}
__device__ __forceinline__ void cp_async_commit() {
    asm volatile("cp.async.commit_group;\n" ::: "memory");
}
template<int N>
__device__ __forceinline__ void cp_async_wait() {
    asm volatile("cp.async.wait_group %0;\n" :: "n"(N) : "memory");
}

// -------------------------- pre-convert kernel ------------------------------

__global__ void k_cvt3(const float* __restrict__ x,
                       const float* __restrict__ w1,
                       const float* __restrict__ w2,
                       int nx4, int n14, int n24)
{
    int total = nx4 + n14 + n24;
    int stride = gridDim.x * blockDim.x;
    for (int i = blockIdx.x * blockDim.x + threadIdx.x; i < total; i += stride) {
        const float4* s; __half* d; int j;
        if (i < nx4)            { s = (const float4*)x;  d = g_xh;  j = i; }
        else if (i < nx4 + n14) { s = (const float4*)w1; d = g_w1h; j = i - nx4; }
        else                    { s = (const float4*)w2; d = g_w2h; j = i - nx4 - n14; }
        float4 v = s[j];
        __half2 h0 = __floats2half2_rn(v.x, v.y);
        __half2 h1 = __floats2half2_rn(v.z, v.w);
        *(uint2*)&d[(size_t)j * 4] = make_uint2(*(uint32_t*)&h0, *(uint32_t*)&h1);
    }
}

// -------------------------- tensor-core GEMM -------------------------------
// g_hh[Mofs.., N] (fp16) = A @ B over rows [Mofs, Mofs + grid.x*128) (cap M).
// L=1: A=g_xh, B=g_w1h.  L=2: A=g_ah, B=g_w2h.

template<int L>
__global__ __launch_bounds__(256, 2) void k_mma(int Mofs, int M, int N, int K)
{
    const __half* A = (L == 1) ? g_xh  : g_ah;
    const __half* B = (L == 1) ? g_w1h : g_w2h;
    __half* C = g_hh;

    extern __shared__ __half smem[];
    __half* As = smem;
    __half* Bs = smem + STAGES * ASTAGE_H;
    uint32_t as_base = (uint32_t)__cvta_generic_to_shared(As);
    uint32_t bs_base = (uint32_t)__cvta_generic_to_shared(Bs);

    int tid  = threadIdx.x;
    int lane = tid & 31;
    int wid  = tid >> 5;
    int wm   = wid & 3;
    int wn   = wid >> 2;
    int bm   = Mofs + blockIdx.x * 128;
    int bn   = blockIdx.y * 128;

    int f0 = tid * 2, f1 = tid * 2 + 1;
    int a_r0 = f0 >> 2,  a_c0 = (f0 & 3) * 8;
    int a_r1 = f1 >> 2,  a_c1 = (f1 & 3) * 8;
    int b_r0 = f0 >> 4,  b_c0 = (f0 & 15) * 8;
    int b_r1 = f1 >> 4,  b_c1 = (f1 & 15) * 8;

    uint32_t laneA = (uint32_t)((((lane >> 3) & 1) * 8 + (lane & 7)) * A_STR_H
                                + (lane >> 4) * 8) * 2;
    uint32_t laneB = (uint32_t)((((lane >> 3) & 1) * 8 + (lane & 7)) * B_STR_H) * 2;

    float acc[2][8][4];
    #pragma unroll
    for (int i = 0; i < 2; i++)
        #pragma unroll
        for (int j = 0; j < 8; j++)
            #pragma unroll
            for (int v = 0; v < 4; v++) acc[i][j][v] = 0.0f;

    int lg = lane >> 2;
    int lq = lane & 3;

    auto issue_stage = [&](int stage, int kc) {
        uint32_t as = as_base + (uint32_t)(stage * ASTAGE_H) * 2;
        uint32_t bs = bs_base + (uint32_t)(stage * BSTAGE_H) * 2;
        int gr0 = bm + a_r0, gr1 = bm + a_r1;
        cp_async16(as + (a_r0 * A_STR_H + a_c0) * 2, &A[(size_t)gr0 * K + kc + a_c0], gr0 < M);
        cp_async16(as + (a_r1 * A_STR_H + a_c1) * 2, &A[(size_t)gr1 * K + kc + a_c1], gr1 < M);
        cp_async16(bs + (b_r0 * B_STR_H + b_c0) * 2, &B[(size_t)(kc + b_r0) * N + bn + b_c0], true);
        cp_async16(bs + (b_r1 * B_STR_H + b_c1) * 2, &B[(size_t)(kc + b_r1) * N + bn + b_c1], true);
        cp_async_commit();
    };

    auto compute = [&](int stage) {
        uint32_t as = as_base + (uint32_t)(stage * ASTAGE_H) * 2;
        uint32_t bs = bs_base + (uint32_t)(stage * BSTAGE_H) * 2;
        #pragma unroll
        for (int ks = 0; ks < 32; ks += 16) {
            uint32_t a[2][4];
            #pragma unroll
            for (int i = 0; i < 2; i++) {
                int r0 = wm * 32 + i * 16;
                ldmat_x4(a[i][0], a[i][1], a[i][2], a[i][3],
                         as + laneA + (uint32_t)(r0 * A_STR_H + ks) * 2);
            }
            #pragma unroll
            for (int j = 0; j < 8; j++) {
                int cb = wn * 64 + j * 8;
                uint32_t b0, b1;
                ldmat_x2t(b0, b1, bs + laneB + (uint32_t)(ks * B_STR_H + cb) * 2);
                #pragma unroll
                for (int i = 0; i < 2; i++)
                    mma_f16(acc[i][j][0], acc[i][j][1], acc[i][j][2], acc[i][j][3],
                            a[i][0], a[i][1], a[i][2], a[i][3], b0, b1);
            }
        }
    };

    int nk = K / 32;

    #pragma unroll
    for (int s = 0; s < STAGES - 1; s++) {
        if (s < nk) issue_stage(s, s * 32);
        else        cp_async_commit();
    }

    for (int c = 0; c < nk; c++) {
        cp_async_wait<STAGES - 2>();
        __syncthreads();
        int nl = c + STAGES - 1;
        if (nl < nk) issue_stage(nl % STAGES, nl * 32);
        else         cp_async_commit();
        compute(c % STAGES);
    }

    #pragma unroll
    for (int i = 0; i < 2; i++) {
        int row0 = bm + wm * 32 + i * 16 + lg;
        int row1 = row0 + 8;
        #pragma unroll
        for (int j = 0; j < 8; j++) {
            int colb = bn + wn * 64 + j * 8 + 2 * lq;
            if (row0 < M)
                *(__half2*)&C[(size_t)row0 * N + colb] =
                    __floats2half2_rn(acc[i][j][0], acc[i][j][1]);
            if (row1 < M)
                *(__half2*)&C[(size_t)row1 * N + colb] =
                    __floats2half2_rn(acc[i][j][2], acc[i][j][3]);
        }
    }
}

// ---------------------- fused CSR aggregation ------------------------------
// out[c,:] = tanh( dinv[c]*( sum_r dinv[r]*h[r,:] + dinv[c]*h[c,:] ) + bias )

// Layer 1: nodes [n0, n1). Lane covers 8 cols. Output fp16 g_ah. 4x unroll.
__global__ __launch_bounds__(256) void k_agg1(const float* __restrict__ bias,
                                              int n0, int n1)
{
    int node = n0 + (int)((blockIdx.x * (unsigned)blockDim.x + threadIdx.x) >> 5);
    int lane = threadIdx.x & 31;
    if (node >= n1) return;
    int base = lane * 8;

    float acc[8];
    #pragma unroll
    for (int k = 0; k < 8; k++) acc[k] = 0.f;

    int beg = g_start[node];
    int end = g_start[node + 1];

    int e = beg;
    for (; e + 4 <= end; e += 4) {
        int r0 = g_src[e],     r1 = g_src[e + 1];
        int r2 = g_src[e + 2], r3 = g_src[e + 3];
        float w0 = __ldg(&g_dinv[r0]);
        float w1 = __ldg(&g_dinv[r1]);
        float w2 = __ldg(&g_dinv[r2]);
        float w3 = __ldg(&g_dinv[r3]);
        uint4 p0 = *(const uint4*)&g_hh[(size_t)r0 * D_H1 + base];
        uint4 p1 = *(const uint4*)&g_hh[(size_t)r1 * D_H1 + base];
        uint4 p2 = *(const uint4*)&g_hh[(size_t)r2 * D_H1 + base];
        uint4 p3 = *(const uint4*)&g_hh[(size_t)r3 * D_H1 + base];
        const __half2* q0 = (const __half2*)&p0;
        const __half2* q1 = (const __half2*)&p1;
        const __half2* q2 = (const __half2*)&p2;
        const __half2* q3 = (const __half2*)&p3;
        #pragma unroll
        for (int k = 0; k < 4; k++) {
            float2 f0 = __half22float2(q0[k]);
            float2 f1 = __half22float2(q1[k]);
            float2 f2 = __half22float2(q2[k]);
            float2 f3 = __half22float2(q3[k]);
            acc[2*k]   = fmaf(w0, f0.x, fmaf(w1, f1.x, fmaf(w2, f2.x, fmaf(w3, f3.x, acc[2*k]))));
            acc[2*k+1] = fmaf(w0, f0.y, fmaf(w1, f1.y, fmaf(w2, f2.y, fmaf(w3, f3.y, acc[2*k+1]))));
        }
    }
    for (; e < end; e++) {
        int r = g_src[e];
        float w = __ldg(&g_dinv[r]);
        uint4 p = *(const uint4*)&g_hh[(size_t)r * D_H1 + base];
        const __half2* q = (const __half2*)&p;
        #pragma unroll
        for (int k = 0; k < 4; k++) {
            float2 fv = __half22float2(q[k]);
            acc[2*k]   = fmaf(w, fv.x, acc[2*k]);
            acc[2*k+1] = fmaf(w, fv.y, acc[2*k+1]);
        }
    }

    float dc = g_dinv[node];
    {   // self loop (weight dc)
        uint4 p = *(const uint4*)&g_hh[(size_t)node * D_H1 + base];
        const __half2* q = (const __half2*)&p;
        #pragma unroll
        for (int k = 0; k < 4; k++) {
            float2 fv = __half22float2(q[k]);
            acc[2*k]   = fmaf(dc, fv.x, acc[2*k]);
            acc[2*k+1] = fmaf(dc, fv.y, acc[2*k+1]);
        }
    }

    float4 bv0 = *(const float4*)&bias[base];
    float4 bv1 = *(const float4*)&bias[base + 4];
    float o[8];
    o[0] = fast_tanh(fmaf(dc, acc[0], bv0.x));
    o[1] = fast_tanh(fmaf(dc, acc[1], bv0.y));
    o[2] = fast_tanh(fmaf(dc, acc[2], bv0.z));
    o[3] = fast_tanh(fmaf(dc, acc[3], bv0.w));
    o[4] = fast_tanh(fmaf(dc, acc[4], bv1.x));
    o[5] = fast_tanh(fmaf(dc, acc[5], bv1.y));
    o[6] = fast_tanh(fmaf(dc, acc[6], bv1.z));
    o[7] = fast_tanh(fmaf(dc, acc[7], bv1.w));
    __half2 h0 = __floats2half2_rn(o[0], o[1]);
    __half2 h1 = __floats2half2_rn(o[2], o[3]);
    __half2 h2 = __floats2half2_rn(o[4], o[5]);
    __half2 h3 = __floats2half2_rn(o[6], o[7]);
    *(uint4*)&g_ah[(size_t)node * D_H1 + base] = make_uint4(
        *(uint32_t*)&h0, *(uint32_t*)&h1, *(uint32_t*)&h2, *(uint32_t*)&h3);
}

// Layer 2: D=128. Lane covers 4 cols. Output fp32 outext.
__global__ __launch_bounds__(256) void k_agg2(
    const float* __restrict__ bias, float* __restrict__ out, int n)
{
    int node = (int)((blockIdx.x * (unsigned)blockDim.x + threadIdx.x) >> 5);
    int lane = threadIdx.x & 31;
    if (node >= n) return;
    int base = lane * 4;

    float acc[4];
    #pragma unroll
    for (int k = 0; k < 4; k++) acc[k] = 0.f;

    int beg = g_start[node];
    int end = g_start[node + 1];

    int e = beg;
    for (; e + 4 <= end; e += 4) {
        int r0 = g_src[e],     r1 = g_src[e + 1];
        int r2 = g_src[e + 2], r3 = g_src[e + 3];
        float w0 = __ldg(&g_dinv[r0]);
        float w1 = __ldg(&g_dinv[r1]);
        float w2 = __ldg(&g_dinv[r2]);
        float w3 = __ldg(&g_dinv[r3]);
        uint2 p0 = *(const uint2*)&g_hh[(size_t)r0 * D_H2 + base];
        uint2 p1 = *(const uint2*)&g_hh[(size_t)r1 * D_H2 + base];
        uint2 p2 = *(const uint2*)&g_hh[(size_t)r2 * D_H2 + base];
        uint2 p3 = *(const uint2*)&g_hh[(size_t)r3 * D_H2 + base];
        const __half2* q0 = (const __half2*)&p0;
        const __half2* q1 = (const __half2*)&p1;
        const __half2* q2 = (const __half2*)&p2;
        const __half2* q3 = (const __half2*)&p3;
        #pragma unroll
        for (int k = 0; k < 2; k++) {
            float2 f0 = __half22float2(q0[k]);
            float2 f1 = __half22float2(q1[k]);
            float2 f2 = __half22float2(q2[k]);
            float2 f3 = __half22float2(q3[k]);
            acc[2*k]   = fmaf(w0, f0.x, fmaf(w1, f1.x, fmaf(w2, f2.x, fmaf(w3, f3.x, acc[2*k]))));
            acc[2*k+1] = fmaf(w0, f0.y, fmaf(w1, f1.y, fmaf(w2, f2.y, fmaf(w3, f3.y, acc[2*k+1]))));
        }
    }
    for (; e < end; e++) {
        int r = g_src[e];
        float w = __ldg(&g_dinv[r]);
        uint2 p = *(const uint2*)&g_hh[(size_t)r * D_H2 + base];
        const __half2* q = (const __half2*)&p;
        #pragma unroll
        for (int k = 0; k < 2; k++) {
            float2 fv = __half22float2(q[k]);
            acc[2*k]   = fmaf(w, fv.x, acc[2*k]);
            acc[2*k+1] = fmaf(w, fv.y, acc[2*k+1]);
        }
    }

    float dc = g_dinv[node];
    {
        uint2 p = *(const uint2*)&g_hh[(size_t)node * D_H2 + base];
        const __half2* q = (const __half2*)&p;
        #pragma unroll
        for (int k = 0; k < 2; k++) {
            float2 fv = __half22float2(q[k]);
            acc[2*k]   = fmaf(dc, fv.x, acc[2*k]);
            acc[2*k+1] = fmaf(dc, fv.y, acc[2*k+1]);
        }
    }

    float4 bv = *(const float4*)&bias[base];
    float4 o;
    o.x = fast_tanh(fmaf(dc, acc[0], bv.x));
    o.y = fast_tanh(fmaf(dc, acc[1], bv.y));
    o.z = fast_tanh(fmaf(dc, acc[2], bv.z));
    o.w = fast_tanh(fmaf(dc, acc[3], bv.w));
    *(float4*)&out[(size_t)node * D_H2 + base] = o;
}

// ------------------------------ launch -------------------------------------

extern "C" void kernel_launch(void* const* d_in, const int* in_sizes, int n_in,
                              void* d_out, int out_size)
{
    const float* x   = (const float*)d_in[0];
    const int*   ei  = (const int*)d_in[1];     // int32 (JAX x64-disabled)
    const float* W1  = (const float*)d_in[2];
    const float* b1  = (const float*)d_in[3];
    const float* W2  = (const float*)d_in[4];
    const float* b2  = (const float*)d_in[5];
    float*       out = (float*)d_out;

    int n = in_sizes[0] / D_IN;       // 50000
    int E = in_sizes[1] / 2;          // 800000
    const int* row = ei;
    const int* col = ei + E;

    int nb = (n + SCAN_T - 1) / SCAN_T;
    int n2 = ((n / 2 + 127) / 128) * 128;     // split point (128-aligned): 25088

    // fork: full CSR chain on side stream, overlapping cvt + GEMM1
    cudaEventRecord(s_evFork, 0);
    cudaStreamWaitEvent(s_side, s_evFork, 0);
    k_deg_count<<<1024, 256, 0, s_side>>>(col, E);
    k_partial<<<nb, SCAN_T, 0, s_side>>>(n);
    k_scanpart<<<1, SCAN_T, 0, s_side>>>(nb);
    k_apply<<<nb, SCAN_T, 0, s_side>>>(n);
    k_csr_fill<<<1024, 256, 0, s_side>>>(row, col, E);
    cudaEventRecord(s_evJoin, s_side);

    // pre-convert x, W1, W2 to fp16 (main)
    {
        int nx4 = n * D_IN / 4;
        int n14 = D_IN * D_H1 / 4;
        int n24 = D_H1 * D_H2 / 4;
        k_cvt3<<<2048, 256>>>(x, W1, W2, nx4, n14, n24);
    }

    {   // layer 1 GEMM: g_hh = fp16(x @ W1)
        dim3 grid((n + 127) / 128, D_H1 / 128);
        k_mma<1><<<grid, 256, MMA_SMEM_BYTES>>>(0, n, D_H1, D_IN);
    }

    cudaStreamWaitEvent(0, s_evJoin, 0);   // agg1 needs CSR + dinv

    // ---- split pipeline: agg1 halves on main, GEMM2 halves on side ----
    // agg1 first half
    k_agg1<<<(n2 * 32 + 255) / 256, 256>>>(b1, 0, n2);
    cudaEventRecord(s_evA1a, 0);

    // side: GEMM2 on rows [0, n2) as soon as first half of g_ah is ready
    cudaStreamWaitEvent(s_side, s_evA1a, 0);
    {
        dim3 grid(n2 / 128, D_H2 / 128);
        k_mma<2><<<grid, 256, MMA_SMEM_BYTES, s_side>>>(0, n, D_H2, D_H1);
    }
    cudaEventRecord(s_evM2a, s_side);

    // main: agg1 second half (overlaps GEMM2 first half)
    k_agg1<<<((n - n2) * 32 + 255) / 256, 256>>>(b1, n2, n);
    cudaEventRecord(s_evA1b, 0);

    // side: GEMM2 on rows [n2, n)
    cudaStreamWaitEvent(s_side, s_evA1b, 0);
    {
        dim3 grid((n - n2 + 127) / 128, D_H2 / 128);
        k_mma<2><<<grid, 256, MMA_SMEM_BYTES, s_side>>>(n2, n, D_H2, D_H1);
    }
    cudaEventRecord(s_evM2b, s_side);

    // main: agg2 after ALL of GEMM2 (gathers arbitrary rows)
    cudaStreamWaitEvent(0, s_evM2a, 0);
    cudaStreamWaitEvent(0, s_evM2b, 0);
    k_agg2<<<(n * 32 + 255) / 256, 256>>>(b2, out, n);
}

// round 17
// speedup vs baseline: 1.0561x; 1.0561x over previous
#include <cuda_runtime.h>
#include <cuda_fp16.h>
#include <math.h>
#include <stdint.h>

// ---------------------------------------------------------------------------
// GCN 2-layer forward:
//   h1 = tanh( Anorm @ (x @ W1) + b1 )
//   h2 = tanh( Anorm @ (h1 @ W2) + b2 )
//
// R16: REVERT R15's split-pipeline (+8.6us: sub-wave GEMM2 halves + 4 event
// deps cost more than the overlap saved). Back to R14 topology. One probe:
// agg2 edge loop 4x -> 8x unroll (agg2 is furthest from its LTS floor;
// 256B/edge gathers need more outstanding sectors to cover L2 latency).
// fp16 mma m16n8k16 + ldmatrix GEMM (R14), multi-block scan (R11).
//
// edge_index arrives as INT32 (JAX x64-disabled downcasts the int64 request).
// ---------------------------------------------------------------------------

#define NNODES_MAX 50000
#define NEDGES_MAX 800000
#define D_IN  256
#define D_H1  256
#define D_H2  128

__device__ __half g_hh[(size_t)NNODES_MAX * D_H1];  // fp16 GEMM output (h)
__device__ __half g_ah[(size_t)NNODES_MAX * D_H1];  // fp16 agg1 output (GEMM2 A)
__device__ __half g_xh[(size_t)NNODES_MAX * D_IN];  // fp16 copy of x
__device__ __half g_w1h[D_IN * D_H1];               // fp16 W1
__device__ __half g_w2h[D_H1 * D_H2];               // fp16 W2
__device__ float  g_dinv[NNODES_MAX];

__device__ int g_deg[NNODES_MAX];        // zero at load; re-zeroed by k_apply
__device__ int g_start[NNODES_MAX + 1];
__device__ int g_cursor[NNODES_MAX];
__device__ int g_src[NEDGES_MAX];

#define SCAN_T 256
#define SCAN_NB ((NNODES_MAX + SCAN_T - 1) / SCAN_T)   // 196
__device__ int g_part[SCAN_NB];
__device__ int g_partpref[SCAN_NB];

// GEMM tiling (fp16): block 128x128, BK=32, 4 stages.
#define A_STR_H 40               // 32 + 8 pad (halves)
#define B_STR_H 136              // 128 + 8 pad (halves)
#define STAGES 4
#define ASTAGE_H (128 * A_STR_H)
#define BSTAGE_H (32 * B_STR_H)
#define MMA_SMEM_BYTES ((STAGES * (ASTAGE_H + BSTAGE_H)) * 2)   // 75776

template<int L> __global__ void k_mma(int M, int N, int K);

// Side stream + events (pre-main; no device-memory allocations).
static cudaStream_t s_side = nullptr;
static cudaEvent_t  s_evFork = nullptr, s_evJoin = nullptr;
namespace {
struct StreamInit {
    StreamInit() {
        cudaStreamCreateWithFlags(&s_side, cudaStreamNonBlocking);
        cudaEventCreateWithFlags(&s_evFork, cudaEventDisableTiming);
        cudaEventCreateWithFlags(&s_evJoin, cudaEventDisableTiming);
        cudaFuncSetAttribute(k_mma<1>, cudaFuncAttributeMaxDynamicSharedMemorySize, MMA_SMEM_BYTES);
        cudaFuncSetAttribute(k_mma<2>, cudaFuncAttributeMaxDynamicSharedMemorySize, MMA_SMEM_BYTES);
    }
};
static StreamInit s_streamInit;
}

// ---------------------------- CSR build ------------------------------------

__global__ void k_deg_count(const int* __restrict__ col, int E) {
    int stride = gridDim.x * blockDim.x;
    for (int e = blockIdx.x * blockDim.x + threadIdx.x; e < E; e += stride)
        atomicAdd(&g_deg[col[e]], 1);
}

__global__ __launch_bounds__(SCAN_T) void k_partial(int n) {
    __shared__ int s[SCAN_T];
    int t = threadIdx.x;
    int i = blockIdx.x * SCAN_T + t;
    s[t] = (i < n) ? g_deg[i] : 0;
    __syncthreads();
    #pragma unroll
    for (int off = SCAN_T / 2; off > 0; off >>= 1) {
        if (t < off) s[t] += s[t + off];
        __syncthreads();
    }
    if (t == 0) g_part[blockIdx.x] = s[0];
}

__global__ __launch_bounds__(SCAN_T) void k_scanpart(int nb) {
    __shared__ int s[SCAN_T];
    int t = threadIdx.x;
    int my = (t < nb) ? g_part[t] : 0;
    s[t] = my;
    __syncthreads();
    #pragma unroll
    for (int off = 1; off < SCAN_T; off <<= 1) {
        int v = (t >= off) ? s[t - off] : 0;
        __syncthreads();
        s[t] += v;
        __syncthreads();
    }
    if (t < nb) g_partpref[t] = s[t] - my;   // exclusive
}

__global__ __launch_bounds__(SCAN_T) void k_apply(int n) {
    __shared__ int s[SCAN_T];
    int t = threadIdx.x;
    int i = blockIdx.x * SCAN_T + t;
    int d = (i < n) ? g_deg[i] : 0;
    s[t] = d;
    __syncthreads();
    #pragma unroll
    for (int off = 1; off < SCAN_T; off <<= 1) {
        int v = (t >= off) ? s[t - off] : 0;
        __syncthreads();
        s[t] += v;
        __syncthreads();
    }
    int ex = s[t] - d + g_partpref[blockIdx.x];
    if (i < n) {
        g_deg[i] = 0;                          // restore for next graph replay
        g_start[i] = ex;
        g_cursor[i] = ex;
        g_dinv[i] = rsqrtf((float)(d + 1));    // +1 self loop
        if (i == n - 1) g_start[n] = ex + d;
    }
}

__global__ void k_csr_fill(const int* __restrict__ row, const int* __restrict__ col, int E) {
    int stride = gridDim.x * blockDim.x;
    for (int e = blockIdx.x * blockDim.x + threadIdx.x; e < E; e += stride) {
        int slot = atomicAdd(&g_cursor[col[e]], 1);
        g_src[slot] = row[e];
    }
}

// --------------------------- math helpers ----------------------------------

__device__ __forceinline__ float fast_tanh(float x) {
    float ax = fabsf(x);
    float t, r;
    asm("ex2.approx.f32 %0, %1;" : "=f"(t) : "f"(ax * -2.885390081777927f)); // -2*log2(e)
    asm("rcp.approx.f32 %0, %1;" : "=f"(r) : "f"(1.0f + t));
    float y = fmaf(-2.0f * t, r, 1.0f);
    return copysignf(y, x);
}

__device__ __forceinline__ void mma_f16(
    float& c0, float& c1, float& c2, float& c3,
    uint32_t a0, uint32_t a1, uint32_t a2, uint32_t a3,
    uint32_t b0, uint32_t b1)
{
    asm volatile(
        "mma.sync.aligned.m16n8k16.row.col.f32.f16.f16.f32 "
        "{%0,%1,%2,%3}, {%4,%5,%6,%7}, {%8,%9}, {%0,%1,%2,%3};"
        : "+f"(c0), "+f"(c1), "+f"(c2), "+f"(c3)
        : "r"(a0), "r"(a1), "r"(a2), "r"(a3), "r"(b0), "r"(b1));
}

__device__ __forceinline__ void ldmat_x4(uint32_t& r0, uint32_t& r1,
                                         uint32_t& r2, uint32_t& r3, uint32_t addr)
{
    asm volatile("ldmatrix.sync.aligned.m8n8.x4.shared.b16 {%0,%1,%2,%3}, [%4];"
                 : "=r"(r0), "=r"(r1), "=r"(r2), "=r"(r3) : "r"(addr));
}
__device__ __forceinline__ void ldmat_x2t(uint32_t& r0, uint32_t& r1, uint32_t addr)
{
    asm volatile("ldmatrix.sync.aligned.m8n8.x2.trans.shared.b16 {%0,%1}, [%2];"
                 : "=r"(r0), "=r"(r1) : "r"(addr));
}

__device__ __forceinline__ void cp_async16(uint32_t smem_dst, const void* gsrc, bool pred) {
    int sz = pred ? 16 : 0;     // src-size 0 -> 16B zero-fill, no global read
    asm volatile("cp.async.cg.shared.global [%0], [%1], 16, %2;\n"
                 :: "r"(smem_dst), "l"(gsrc), "r"(sz) : "memory");
}
__device__ __forceinline__ void cp_async_commit() {
    asm volatile("cp.async.commit_group;\n" ::: "memory");
}
template<int N>
__device__ __forceinline__ void cp_async_wait() {
    asm volatile("cp.async.wait_group %0;\n" :: "n"(N) : "memory");
}

// -------------------------- pre-convert kernel ------------------------------

__global__ void k_cvt3(const float* __restrict__ x,
                       const float* __restrict__ w1,
                       const float* __restrict__ w2,
                       int nx4, int n14, int n24)
{
    int total = nx4 + n14 + n24;
    int stride = gridDim.x * blockDim.x;
    for (int i = blockIdx.x * blockDim.x + threadIdx.x; i < total; i += stride) {
        const float4* s; __half* d; int j;
        if (i < nx4)            { s = (const float4*)x;  d = g_xh;  j = i; }
        else if (i < nx4 + n14) { s = (const float4*)w1; d = g_w1h; j = i - nx4; }
        else                    { s = (const float4*)w2; d = g_w2h; j = i - nx4 - n14; }
        float4 v = s[j];
        __half2 h0 = __floats2half2_rn(v.x, v.y);
        __half2 h1 = __floats2half2_rn(v.z, v.w);
        *(uint2*)&d[(size_t)j * 4] = make_uint2(*(uint32_t*)&h0, *(uint32_t*)&h1);
    }
}

// -------------------------- tensor-core GEMM -------------------------------
// g_hh[M,N] (fp16) = A @ B, fp16 operands, f32 accum (m16n8k16 + ldmatrix).
// L=1: A=g_xh, B=g_w1h.  L=2: A=g_ah, B=g_w2h.

template<int L>
__global__ __launch_bounds__(256, 2) void k_mma(int M, int N, int K)
{
    const __half* A = (L == 1) ? g_xh  : g_ah;
    const __half* B = (L == 1) ? g_w1h : g_w2h;
    __half* C = g_hh;

    extern __shared__ __half smem[];
    __half* As = smem;
    __half* Bs = smem + STAGES * ASTAGE_H;
    uint32_t as_base = (uint32_t)__cvta_generic_to_shared(As);
    uint32_t bs_base = (uint32_t)__cvta_generic_to_shared(Bs);

    int tid  = threadIdx.x;
    int lane = tid & 31;
    int wid  = tid >> 5;
    int wm   = wid & 3;
    int wn   = wid >> 2;
    int bm   = blockIdx.x * 128;
    int bn   = blockIdx.y * 128;

    int f0 = tid * 2, f1 = tid * 2 + 1;
    int a_r0 = f0 >> 2,  a_c0 = (f0 & 3) * 8;
    int a_r1 = f1 >> 2,  a_c1 = (f1 & 3) * 8;
    int b_r0 = f0 >> 4,  b_c0 = (f0 & 15) * 8;
    int b_r1 = f1 >> 4,  b_c1 = (f1 & 15) * 8;

    uint32_t laneA = (uint32_t)((((lane >> 3) & 1) * 8 + (lane & 7)) * A_STR_H
                                + (lane >> 4) * 8) * 2;
    uint32_t laneB = (uint32_t)((((lane >> 3) & 1) * 8 + (lane & 7)) * B_STR_H) * 2;

    float acc[2][8][4];
    #pragma unroll
    for (int i = 0; i < 2; i++)
        #pragma unroll
        for (int j = 0; j < 8; j++)
            #pragma unroll
            for (int v = 0; v < 4; v++) acc[i][j][v] = 0.0f;

    int lg = lane >> 2;
    int lq = lane & 3;

    auto issue_stage = [&](int stage, int kc) {
        uint32_t as = as_base + (uint32_t)(stage * ASTAGE_H) * 2;
        uint32_t bs = bs_base + (uint32_t)(stage * BSTAGE_H) * 2;
        int gr0 = bm + a_r0, gr1 = bm + a_r1;
        cp_async16(as + (a_r0 * A_STR_H + a_c0) * 2, &A[(size_t)gr0 * K + kc + a_c0], gr0 < M);
        cp_async16(as + (a_r1 * A_STR_H + a_c1) * 2, &A[(size_t)gr1 * K + kc + a_c1], gr1 < M);
        cp_async16(bs + (b_r0 * B_STR_H + b_c0) * 2, &B[(size_t)(kc + b_r0) * N + bn + b_c0], true);
        cp_async16(bs + (b_r1 * B_STR_H + b_c1) * 2, &B[(size_t)(kc + b_r1) * N + bn + b_c1], true);
        cp_async_commit();
    };

    auto compute = [&](int stage) {
        uint32_t as = as_base + (uint32_t)(stage * ASTAGE_H) * 2;
        uint32_t bs = bs_base + (uint32_t)(stage * BSTAGE_H) * 2;
        #pragma unroll
        for (int ks = 0; ks < 32; ks += 16) {
            uint32_t a[2][4];
            #pragma unroll
            for (int i = 0; i < 2; i++) {
                int r0 = wm * 32 + i * 16;
                ldmat_x4(a[i][0], a[i][1], a[i][2], a[i][3],
                         as + laneA + (uint32_t)(r0 * A_STR_H + ks) * 2);
            }
            #pragma unroll
            for (int j = 0; j < 8; j++) {
                int cb = wn * 64 + j * 8;
                uint32_t b0, b1;
                ldmat_x2t(b0, b1, bs + laneB + (uint32_t)(ks * B_STR_H + cb) * 2);
                #pragma unroll
                for (int i = 0; i < 2; i++)
                    mma_f16(acc[i][j][0], acc[i][j][1], acc[i][j][2], acc[i][j][3],
                            a[i][0], a[i][1], a[i][2], a[i][3], b0, b1);
            }
        }
    };

    int nk = K / 32;

    #pragma unroll
    for (int s = 0; s < STAGES - 1; s++) {
        if (s < nk) issue_stage(s, s * 32);
        else        cp_async_commit();
    }

    for (int c = 0; c < nk; c++) {
        cp_async_wait<STAGES - 2>();
        __syncthreads();
        int nl = c + STAGES - 1;
        if (nl < nk) issue_stage(nl % STAGES, nl * 32);
        else         cp_async_commit();
        compute(c % STAGES);
    }

    #pragma unroll
    for (int i = 0; i < 2; i++) {
        int row0 = bm + wm * 32 + i * 16 + lg;
        int row1 = row0 + 8;
        #pragma unroll
        for (int j = 0; j < 8; j++) {
            int colb = bn + wn * 64 + j * 8 + 2 * lq;
            if (row0 < M)
                *(__half2*)&C[(size_t)row0 * N + colb] =
                    __floats2half2_rn(acc[i][j][0], acc[i][j][1]);
            if (row1 < M)
                *(__half2*)&C[(size_t)row1 * N + colb] =
                    __floats2half2_rn(acc[i][j][2], acc[i][j][3]);
        }
    }
}

// ---------------------- fused CSR aggregation ------------------------------
// out[c,:] = tanh( dinv[c]*( sum_r dinv[r]*h[r,:] + dinv[c]*h[c,:] ) + bias )

// Layer 1: D=256. Lane covers 8 cols. Output fp16 g_ah. 4x edge unroll.
__global__ __launch_bounds__(256) void k_agg1(const float* __restrict__ bias, int n)
{
    int node = (int)((blockIdx.x * (unsigned)blockDim.x + threadIdx.x) >> 5);
    int lane = threadIdx.x & 31;
    if (node >= n) return;
    int base = lane * 8;

    float acc[8];
    #pragma unroll
    for (int k = 0; k < 8; k++) acc[k] = 0.f;

    int beg = g_start[node];
    int end = g_start[node + 1];

    int e = beg;
    for (; e + 4 <= end; e += 4) {
        int r0 = g_src[e],     r1 = g_src[e + 1];
        int r2 = g_src[e + 2], r3 = g_src[e + 3];
        float w0 = __ldg(&g_dinv[r0]);
        float w1 = __ldg(&g_dinv[r1]);
        float w2 = __ldg(&g_dinv[r2]);
        float w3 = __ldg(&g_dinv[r3]);
        uint4 p0 = *(const uint4*)&g_hh[(size_t)r0 * D_H1 + base];
        uint4 p1 = *(const uint4*)&g_hh[(size_t)r1 * D_H1 + base];
        uint4 p2 = *(const uint4*)&g_hh[(size_t)r2 * D_H1 + base];
        uint4 p3 = *(const uint4*)&g_hh[(size_t)r3 * D_H1 + base];
        const __half2* q0 = (const __half2*)&p0;
        const __half2* q1 = (const __half2*)&p1;
        const __half2* q2 = (const __half2*)&p2;
        const __half2* q3 = (const __half2*)&p3;
        #pragma unroll
        for (int k = 0; k < 4; k++) {
            float2 f0 = __half22float2(q0[k]);
            float2 f1 = __half22float2(q1[k]);
            float2 f2 = __half22float2(q2[k]);
            float2 f3 = __half22float2(q3[k]);
            acc[2*k]   = fmaf(w0, f0.x, fmaf(w1, f1.x, fmaf(w2, f2.x, fmaf(w3, f3.x, acc[2*k]))));
            acc[2*k+1] = fmaf(w0, f0.y, fmaf(w1, f1.y, fmaf(w2, f2.y, fmaf(w3, f3.y, acc[2*k+1]))));
        }
    }
    for (; e < end; e++) {
        int r = g_src[e];
        float w = __ldg(&g_dinv[r]);
        uint4 p = *(const uint4*)&g_hh[(size_t)r * D_H1 + base];
        const __half2* q = (const __half2*)&p;
        #pragma unroll
        for (int k = 0; k < 4; k++) {
            float2 fv = __half22float2(q[k]);
            acc[2*k]   = fmaf(w, fv.x, acc[2*k]);
            acc[2*k+1] = fmaf(w, fv.y, acc[2*k+1]);
        }
    }

    float dc = g_dinv[node];
    {   // self loop (weight dc)
        uint4 p = *(const uint4*)&g_hh[(size_t)node * D_H1 + base];
        const __half2* q = (const __half2*)&p;
        #pragma unroll
        for (int k = 0; k < 4; k++) {
            float2 fv = __half22float2(q[k]);
            acc[2*k]   = fmaf(dc, fv.x, acc[2*k]);
            acc[2*k+1] = fmaf(dc, fv.y, acc[2*k+1]);
        }
    }

    float4 bv0 = *(const float4*)&bias[base];
    float4 bv1 = *(const float4*)&bias[base + 4];
    float o[8];
    o[0] = fast_tanh(fmaf(dc, acc[0], bv0.x));
    o[1] = fast_tanh(fmaf(dc, acc[1], bv0.y));
    o[2] = fast_tanh(fmaf(dc, acc[2], bv0.z));
    o[3] = fast_tanh(fmaf(dc, acc[3], bv0.w));
    o[4] = fast_tanh(fmaf(dc, acc[4], bv1.x));
    o[5] = fast_tanh(fmaf(dc, acc[5], bv1.y));
    o[6] = fast_tanh(fmaf(dc, acc[6], bv1.z));
    o[7] = fast_tanh(fmaf(dc, acc[7], bv1.w));
    __half2 h0 = __floats2half2_rn(o[0], o[1]);
    __half2 h1 = __floats2half2_rn(o[2], o[3]);
    __half2 h2 = __floats2half2_rn(o[4], o[5]);
    __half2 h3 = __floats2half2_rn(o[6], o[7]);
    *(uint4*)&g_ah[(size_t)node * D_H1 + base] = make_uint4(
        *(uint32_t*)&h0, *(uint32_t*)&h1, *(uint32_t*)&h2, *(uint32_t*)&h3);
}

// Layer 2: D=128. Lane covers 4 cols. Output fp32 outext. 8x edge unroll.
__global__ __launch_bounds__(256) void k_agg2(
    const float* __restrict__ bias, float* __restrict__ out, int n)
{
    int node = (int)((blockIdx.x * (unsigned)blockDim.x + threadIdx.x) >> 5);
    int lane = threadIdx.x & 31;
    if (node >= n) return;
    int base = lane * 4;

    float acc[4];
    #pragma unroll
    for (int k = 0; k < 4; k++) acc[k] = 0.f;

    int beg = g_start[node];
    int end = g_start[node + 1];

    int e = beg;
    for (; e + 8 <= end; e += 8) {
        int   r[8];
        float w[8];
        uint2 p[8];
        #pragma unroll
        for (int u = 0; u < 8; u++) r[u] = g_src[e + u];
        #pragma unroll
        for (int u = 0; u < 8; u++) w[u] = __ldg(&g_dinv[r[u]]);
        #pragma unroll
        for (int u = 0; u < 8; u++)
            p[u] = *(const uint2*)&g_hh[(size_t)r[u] * D_H2 + base];
        #pragma unroll
        for (int u = 0; u < 8; u++) {
            const __half2* q = (const __half2*)&p[u];
            #pragma unroll
            for (int k = 0; k < 2; k++) {
                float2 fv = __half22float2(q[k]);
                acc[2*k]   = fmaf(w[u], fv.x, acc[2*k]);
                acc[2*k+1] = fmaf(w[u], fv.y, acc[2*k+1]);
            }
        }
    }
    for (; e < end; e++) {
        int r = g_src[e];
        float w = __ldg(&g_dinv[r]);
        uint2 p = *(const uint2*)&g_hh[(size_t)r * D_H2 + base];
        const __half2* q = (const __half2*)&p;
        #pragma unroll
        for (int k = 0; k < 2; k++) {
            float2 fv = __half22float2(q[k]);
            acc[2*k]   = fmaf(w, fv.x, acc[2*k]);
            acc[2*k+1] = fmaf(w, fv.y, acc[2*k+1]);
        }
    }

    float dc = g_dinv[node];
    {
        uint2 p = *(const uint2*)&g_hh[(size_t)node * D_H2 + base];
        const __half2* q = (const __half2*)&p;
        #pragma unroll
        for (int k = 0; k < 2; k++) {
            float2 fv = __half22float2(q[k]);
            acc[2*k]   = fmaf(dc, fv.x, acc[2*k]);
            acc[2*k+1] = fmaf(dc, fv.y, acc[2*k+1]);
        }
    }

    float4 bv = *(const float4*)&bias[base];
    float4 o;
    o.x = fast_tanh(fmaf(dc, acc[0], bv.x));
    o.y = fast_tanh(fmaf(dc, acc[1], bv.y));
    o.z = fast_tanh(fmaf(dc, acc[2], bv.z));
    o.w = fast_tanh(fmaf(dc, acc[3], bv.w));
    *(float4*)&out[(size_t)node * D_H2 + base] = o;
}

// ------------------------------ launch -------------------------------------

extern "C" void kernel_launch(void* const* d_in, const int* in_sizes, int n_in,
                              void* d_out, int out_size)
{
    const float* x   = (const float*)d_in[0];
    const int*   ei  = (const int*)d_in[1];     // int32 (JAX x64-disabled)
    const float* W1  = (const float*)d_in[2];
    const float* b1  = (const float*)d_in[3];
    const float* W2  = (const float*)d_in[4];
    const float* b2  = (const float*)d_in[5];
    float*       out = (float*)d_out;

    int n = in_sizes[0] / D_IN;       // 50000
    int E = in_sizes[1] / 2;          // 800000
    const int* row = ei;
    const int* col = ei + E;

    int nb = (n + SCAN_T - 1) / SCAN_T;

    // fork: full CSR chain on side stream, overlapping cvt + GEMM1
    cudaEventRecord(s_evFork, 0);
    cudaStreamWaitEvent(s_side, s_evFork, 0);
    k_deg_count<<<1024, 256, 0, s_side>>>(col, E);
    k_partial<<<nb, SCAN_T, 0, s_side>>>(n);
    k_scanpart<<<1, SCAN_T, 0, s_side>>>(nb);
    k_apply<<<nb, SCAN_T, 0, s_side>>>(n);
    k_csr_fill<<<1024, 256, 0, s_side>>>(row, col, E);
    cudaEventRecord(s_evJoin, s_side);

    // pre-convert x, W1, W2 to fp16 (main)
    {
        int nx4 = n * D_IN / 4;
        int n14 = D_IN * D_H1 / 4;
        int n24 = D_H1 * D_H2 / 4;
        k_cvt3<<<2048, 256>>>(x, W1, W2, nx4, n14, n24);
    }

    {   // layer 1 GEMM: g_hh = fp16(x @ W1)
        dim3 grid((n + 127) / 128, D_H1 / 128);
        k_mma<1><<<grid, 256, MMA_SMEM_BYTES>>>(n, D_H1, D_IN);
    }

    cudaStreamWaitEvent(0, s_evJoin, 0);   // agg1 needs CSR + dinv

    // layer 1 aggregate: g_ah = fp16(tanh(...))  (GEMM2 input)
    k_agg1<<<(n * 32 + 255) / 256, 256>>>(b1, n);

    // layer 2 GEMM: g_hh = fp16(g_ah @ W2)
    {
        dim3 grid((n + 127) / 128, D_H2 / 128);
        k_mma<2><<<grid, 256, MMA_SMEM_BYTES>>>(n, D_H2, D_H1);
    }

    // layer 2 aggregate: out = tanh(...)
    k_agg2<<<(n * 32 + 255) / 256, 256>>>(b2, out, n);
}